// round 4
// baseline (speedup 1.0000x reference)
#include <cuda_runtime.h>

#define THREADS 256
#define TILE    256
#define GRID    592

__device__ float g_partial[GRID];

// ---------- packed f32x2 helpers ----------
static __device__ __forceinline__ unsigned long long pk2(float a, float b) {
    unsigned long long r;
    asm("mov.b64 %0, {%1,%2};" : "=l"(r) : "f"(a), "f"(b));
    return r;
}
static __device__ __forceinline__ float2 upk2(unsigned long long v) {
    float2 f;
    asm("mov.b64 {%0,%1}, %2;" : "=f"(f.x), "=f"(f.y) : "l"(v));
    return f;
}
static __device__ __forceinline__ unsigned long long fma2_(unsigned long long a,
                                                           unsigned long long b,
                                                           unsigned long long c) {
    unsigned long long d;
    asm("fma.rn.f32x2 %0, %1, %2, %3;" : "=l"(d) : "l"(a), "l"(b), "l"(c));
    return d;
}
static __device__ __forceinline__ unsigned long long add2_(unsigned long long a,
                                                           unsigned long long b) {
    unsigned long long d;
    asm("add.rn.f32x2 %0, %1, %2;" : "=l"(d) : "l"(a), "l"(b));
    return d;
}
static __device__ __forceinline__ unsigned long long mul2_(unsigned long long a,
                                                           unsigned long long b) {
    unsigned long long d;
    asm("mul.rn.f32x2 %0, %1, %2;" : "=l"(d) : "l"(a), "l"(b));
    return d;
}

// exp(x) for a pair of floats, FMA-pipe only (no MUFU).
// exp(x) = 2^(x*log2e) = 2^n * 2^f, n = round(x*log2e), f in [-0.5,0.5]
static __device__ __forceinline__ unsigned long long exp_pair(unsigned long long x2) {
    const float L2E = 1.4426950408889634f;
    const unsigned long long L2E2 = pk2(L2E, L2E);
    const unsigned long long MAG2 = pk2(12582912.0f, 12582912.0f);   // 1.5*2^23
    const unsigned long long N12  = pk2(-1.0f, -1.0f);
    // deg-5 Taylor of 2^f: c_k = (ln2)^k / k!
    const unsigned long long C52 = pk2(1.3333558e-3f, 1.3333558e-3f);
    const unsigned long long C42 = pk2(9.6181291e-3f, 9.6181291e-3f);
    const unsigned long long C32 = pk2(5.5504109e-2f, 5.5504109e-2f);
    const unsigned long long C22 = pk2(2.4022651e-1f, 2.4022651e-1f);
    const unsigned long long C12 = pk2(6.9314718e-1f, 6.9314718e-1f);
    const unsigned long long C02 = pk2(1.0f, 1.0f);

    unsigned long long r2 = fma2_(x2, L2E2, MAG2);   // r = RN(z + MAGIC)
    unsigned long long d2 = fma2_(r2, N12, MAG2);    // d = MAGIC - r = -n (exact)
    unsigned long long f2 = fma2_(x2, L2E2, d2);     // f = z - n
    unsigned long long p2 = fma2_(C52, f2, C42);
    p2 = fma2_(p2, f2, C32);
    p2 = fma2_(p2, f2, C22);
    p2 = fma2_(p2, f2, C12);
    p2 = fma2_(p2, f2, C02);                         // p = 2^f
    float2 r = upk2(r2);
    // bits(r) = 0x4B400000 + n -> (bits << 23) + 1.0f bits = bits of 2^n
    unsigned ia = (unsigned)__float_as_int(r.x) * 8388608u + 0x3f800000u;
    unsigned ib = (unsigned)__float_as_int(r.y) * 8388608u + 0x3f800000u;
    unsigned long long s2 = pk2(__uint_as_float(ia), __uint_as_float(ib));
    return mul2_(p2, s2);
}

__global__ __launch_bounds__(THREADS)
void cce_main_kernel(const float* __restrict__ logits,
                     const int* __restrict__ targets,
                     int B, int NT) {
    __shared__ float s_log[TILE * 9];
    __shared__ float s_v[81];          // v[t][k] = w[t][k] / S[t]
    __shared__ float s_red[THREADS];

    const int tid = threadIdx.x;

    // Build normalized smoothed-label table (9 threads, once per block).
    if (tid < 9) {
        float w[9];
        float S = 0.0f;
        #pragma unroll
        for (int k = 0; k < 9; k++) {
            float ww;
            if (k == tid) {
                ww = 1.0f - 0.1f - 0.2f;                 // main = 0.7
            } else {
                ww = 0.1f / 9.0f;                        // base
                if (k > tid) ww += 0.2f * exp2f((float)(tid - k));
            }
            w[k] = ww;
            S += ww;
        }
        float inv = 1.0f / S;
        #pragma unroll
        for (int k = 0; k < 9; k++) s_v[tid * 9 + k] = w[k] * inv;
    }

    float acc = 0.0f;

    for (int tile = blockIdx.x; tile < NT; tile += GRID) {
        const int base = tile * TILE;
        const int rows = min(TILE, B - base);

        // Stage logits tile: coalesced float4 loads -> shared.
        if (rows == TILE) {
            const float4* g4 = (const float4*)(logits + (size_t)base * 9);
            #pragma unroll
            for (int i = tid; i < TILE * 9 / 4; i += THREADS)
                ((float4*)s_log)[i] = g4[i];
        } else {
            for (int i = tid; i < rows * 9; i += THREADS)
                s_log[i] = logits[(size_t)base * 9 + i];
        }
        int t = 0;
        if (tid < rows) t = targets[base + tid];
        __syncthreads();

        if (tid < rows) {
            float x[9];
            #pragma unroll
            for (int k = 0; k < 9; k++) x[k] = s_log[tid * 9 + k];

            // exps of 9 logits (+ one padded 0 whose exp==1, subtracted below)
            unsigned long long e01 = exp_pair(pk2(x[0], x[1]));
            unsigned long long e23 = exp_pair(pk2(x[2], x[3]));
            unsigned long long e45 = exp_pair(pk2(x[4], x[5]));
            unsigned long long e67 = exp_pair(pk2(x[6], x[7]));
            unsigned long long e89 = exp_pair(pk2(x[8], 0.0f));
            unsigned long long sA = add2_(e01, e23);
            unsigned long long sB = add2_(e45, e67);
            unsigned long long sT = add2_(add2_(sA, sB), e89);
            float2 sf = upk2(sT);
            float sumExp = (sf.x + sf.y) - 1.0f;
            float lse = __logf(sumExp);

            const float* vr = &s_v[t * 9];
            float dot = 0.0f;
            #pragma unroll
            for (int k = 0; k < 9; k++) dot = fmaf(vr[k], x[k], dot);

            acc += lse - dot;
        }
        __syncthreads();
    }

    // Deterministic block reduction.
    s_red[tid] = acc;
    __syncthreads();
    #pragma unroll
    for (int s = THREADS / 2; s > 0; s >>= 1) {
        if (tid < s) s_red[tid] += s_red[tid + s];
        __syncthreads();
    }
    if (tid == 0) g_partial[blockIdx.x] = s_red[0];
}

__global__ __launch_bounds__(THREADS)
void cce_reduce_kernel(float* __restrict__ out, float invB) {
    __shared__ float s[THREADS];
    const int tid = threadIdx.x;
    float a = 0.0f;
    for (int i = tid; i < GRID; i += THREADS) a += g_partial[i];
    s[tid] = a;
    __syncthreads();
    #pragma unroll
    for (int k = THREADS / 2; k > 0; k >>= 1) {
        if (tid < k) s[tid] += s[tid + k];
        __syncthreads();
    }
    if (tid == 0) out[0] = s[0] * invB;
}

extern "C" void kernel_launch(void* const* d_in, const int* in_sizes, int n_in,
                              void* d_out, int out_size) {
    const float* logits  = (const float*)d_in[0];
    const int*   targets = (const int*)d_in[1];
    const int B  = in_sizes[1];             // number of rows (targets count)
    const int NT = (B + TILE - 1) / TILE;

    cce_main_kernel<<<GRID, THREADS>>>(logits, targets, B, NT);
    cce_reduce_kernel<<<1, THREADS>>>((float*)d_out, 1.0f / (float)B);
}

// round 5
// speedup vs baseline: 1.2531x; 1.2531x over previous
#include <cuda_runtime.h>

#define THREADS 256
#define TILE    512
#define GRID    592

__device__ float g_partial[GRID];
__device__ unsigned g_count = 0;

// ---------- packed f32x2 helpers ----------
static __device__ __forceinline__ unsigned long long pk2(float a, float b) {
    unsigned long long r;
    asm("mov.b64 %0, {%1,%2};" : "=l"(r) : "f"(a), "f"(b));
    return r;
}
static __device__ __forceinline__ float2 upk2(unsigned long long v) {
    float2 f;
    asm("mov.b64 {%0,%1}, %2;" : "=f"(f.x), "=f"(f.y) : "l"(v));
    return f;
}
static __device__ __forceinline__ unsigned long long fma2_(unsigned long long a,
                                                           unsigned long long b,
                                                           unsigned long long c) {
    unsigned long long d;
    asm("fma.rn.f32x2 %0, %1, %2, %3;" : "=l"(d) : "l"(a), "l"(b), "l"(c));
    return d;
}
static __device__ __forceinline__ unsigned long long add2_(unsigned long long a,
                                                           unsigned long long b) {
    unsigned long long d;
    asm("add.rn.f32x2 %0, %1, %2;" : "=l"(d) : "l"(a), "l"(b));
    return d;
}
static __device__ __forceinline__ unsigned long long mul2_(unsigned long long a,
                                                           unsigned long long b) {
    unsigned long long d;
    asm("mul.rn.f32x2 %0, %1, %2;" : "=l"(d) : "l"(a), "l"(b));
    return d;
}

// exp(x) for a pair of floats, FMA-pipe only (no MUFU).
// exp(x) = 2^(x*log2e) = 2^n * 2^f, n = round(x*log2e), f in [-0.5,0.5]
static __device__ __forceinline__ unsigned long long exp_pair(unsigned long long x2) {
    const float L2E = 1.4426950408889634f;
    const unsigned long long L2E2 = pk2(L2E, L2E);
    const unsigned long long MAG2 = pk2(12582912.0f, 12582912.0f);   // 1.5*2^23
    const unsigned long long N12  = pk2(-1.0f, -1.0f);
    // deg-5 Taylor of 2^f: c_k = (ln2)^k / k!
    const unsigned long long C52 = pk2(1.3333558e-3f, 1.3333558e-3f);
    const unsigned long long C42 = pk2(9.6181291e-3f, 9.6181291e-3f);
    const unsigned long long C32 = pk2(5.5504109e-2f, 5.5504109e-2f);
    const unsigned long long C22 = pk2(2.4022651e-1f, 2.4022651e-1f);
    const unsigned long long C12 = pk2(6.9314718e-1f, 6.9314718e-1f);
    const unsigned long long C02 = pk2(1.0f, 1.0f);

    unsigned long long r2 = fma2_(x2, L2E2, MAG2);   // r = RN(z + MAGIC)
    unsigned long long d2 = fma2_(r2, N12, MAG2);    // d = MAGIC - r = -n (exact)
    unsigned long long f2 = fma2_(x2, L2E2, d2);     // f = z - n
    unsigned long long p2 = fma2_(C52, f2, C42);
    p2 = fma2_(p2, f2, C32);
    p2 = fma2_(p2, f2, C22);
    p2 = fma2_(p2, f2, C12);
    p2 = fma2_(p2, f2, C02);                         // p = 2^f
    float2 r = upk2(r2);
    // bits(r) = 0x4B400000 + n -> (bits << 23) + 1.0f bits = bits of 2^n
    unsigned ia = (unsigned)__float_as_int(r.x) * 8388608u + 0x3f800000u;
    unsigned ib = (unsigned)__float_as_int(r.y) * 8388608u + 0x3f800000u;
    unsigned long long s2 = pk2(__uint_as_float(ia), __uint_as_float(ib));
    return mul2_(p2, s2);
}

// Single-row loss (tail path): lse(x) - v[t].x
static __device__ __forceinline__ float row_loss(const float* __restrict__ x,
                                                 const float* __restrict__ vr) {
    unsigned long long e01 = exp_pair(pk2(x[0], x[1]));
    unsigned long long e23 = exp_pair(pk2(x[2], x[3]));
    unsigned long long e45 = exp_pair(pk2(x[4], x[5]));
    unsigned long long e67 = exp_pair(pk2(x[6], x[7]));
    unsigned long long e89 = exp_pair(pk2(x[8], 0.0f));
    unsigned long long sA = add2_(e01, e23);
    unsigned long long sB = add2_(e45, e67);
    unsigned long long sT = add2_(add2_(sA, sB), e89);
    float2 sf = upk2(sT);
    float sumExp = (sf.x + sf.y) - 1.0f;
    float lse = __logf(sumExp);
    float dot = 0.0f;
    #pragma unroll
    for (int k = 0; k < 9; k++) dot = fmaf(vr[k], x[k], dot);
    return lse - dot;
}

__global__ __launch_bounds__(THREADS)
void cce_fused_kernel(const float* __restrict__ logits,
                      const int* __restrict__ targets,
                      float* __restrict__ out,
                      int B, int NT, float invB) {
    __shared__ float s_log[TILE * 9];
    __shared__ float s_v[81];          // v[t][k] = w[t][k] / S[t]
    __shared__ float s_red[THREADS];
    __shared__ bool  s_last;

    const int tid = threadIdx.x;

    // Build normalized smoothed-label table (9 threads, once per block).
    if (tid < 9) {
        float w[9];
        float S = 0.0f;
        #pragma unroll
        for (int k = 0; k < 9; k++) {
            float ww;
            if (k == tid) {
                ww = 1.0f - 0.1f - 0.2f;                 // main = 0.7
            } else {
                ww = 0.1f / 9.0f;                        // base
                if (k > tid) ww += 0.2f * exp2f((float)(tid - k));
            }
            w[k] = ww;
            S += ww;
        }
        float inv = 1.0f / S;
        #pragma unroll
        for (int k = 0; k < 9; k++) s_v[tid * 9 + k] = w[k] * inv;
    }

    float acc = 0.0f;

    for (int tile = blockIdx.x; tile < NT; tile += GRID) {
        const int base = tile * TILE;
        const int rows = min(TILE, B - base);

        // Stage logits tile: coalesced float4 loads -> shared.
        if (rows == TILE) {
            const float4* g4 = (const float4*)(logits + (size_t)base * 9);
            #pragma unroll
            for (int i = tid; i < TILE * 9 / 4; i += THREADS)
                ((float4*)s_log)[i] = g4[i];
        } else {
            for (int i = tid; i < rows * 9; i += THREADS)
                s_log[i] = logits[(size_t)base * 9 + i];
        }
        const int r0 = tid;
        const int r1 = tid + THREADS;
        int t0 = 0, t1 = 0;
        if (r0 < rows) t0 = targets[base + r0];
        if (r1 < rows) t1 = targets[base + r1];
        __syncthreads();

        if (r1 < rows) {
            // Two-row packed path: lane0 <- row r0, lane1 <- row r1.
            float x0[9], x1[9];
            #pragma unroll
            for (int k = 0; k < 9; k++) x0[k] = s_log[r0 * 9 + k];
            #pragma unroll
            for (int k = 0; k < 9; k++) x1[k] = s_log[r1 * 9 + k];

            unsigned long long se2 = exp_pair(pk2(x0[0], x1[0]));
            #pragma unroll
            for (int k = 1; k < 9; k++)
                se2 = add2_(se2, exp_pair(pk2(x0[k], x1[k])));
            float2 se = upk2(se2);
            float lse0 = __logf(se.x);
            float lse1 = __logf(se.y);

            const float* v0 = &s_v[t0 * 9];
            const float* v1 = &s_v[t1 * 9];
            unsigned long long d2 = pk2(0.0f, 0.0f);
            #pragma unroll
            for (int k = 0; k < 9; k++)
                d2 = fma2_(pk2(v0[k], v1[k]), pk2(x0[k], x1[k]), d2);
            float2 dd = upk2(d2);

            acc += (lse0 - dd.x) + (lse1 - dd.y);
        } else if (r0 < rows) {
            float x[9];
            #pragma unroll
            for (int k = 0; k < 9; k++) x[k] = s_log[r0 * 9 + k];
            acc += row_loss(x, &s_v[t0 * 9]);
        }
        __syncthreads();
    }

    // Deterministic block reduction.
    s_red[tid] = acc;
    __syncthreads();
    #pragma unroll
    for (int s = THREADS / 2; s > 0; s >>= 1) {
        if (tid < s) s_red[tid] += s_red[tid + s];
        __syncthreads();
    }
    if (tid == 0) g_partial[blockIdx.x] = s_red[0];

    // Last-block final reduction (fence + counter; counter self-resets so the
    // kernel is replay-deterministic under graph capture).
    if (tid == 0) {
        __threadfence();
        unsigned prev = atomicAdd(&g_count, 1u);
        s_last = (prev == (unsigned)(gridDim.x - 1));
    }
    __syncthreads();
    if (s_last) {
        float a = 0.0f;
        for (int i = tid; i < GRID; i += THREADS) a += g_partial[i];
        s_red[tid] = a;
        __syncthreads();
        #pragma unroll
        for (int s = THREADS / 2; s > 0; s >>= 1) {
            if (tid < s) s_red[tid] += s_red[tid + s];
            __syncthreads();
        }
        if (tid == 0) {
            out[0] = s_red[0] * invB;
            g_count = 0;                 // reset for next graph replay
        }
    }
}

extern "C" void kernel_launch(void* const* d_in, const int* in_sizes, int n_in,
                              void* d_out, int out_size) {
    const float* logits  = (const float*)d_in[0];
    const int*   targets = (const int*)d_in[1];
    const int B  = in_sizes[1];             // number of rows (targets count)
    const int NT = (B + TILE - 1) / TILE;

    cce_fused_kernel<<<GRID, THREADS>>>(logits, targets, (float*)d_out,
                                        B, NT, 1.0f / (float)B);
}

// round 7
// speedup vs baseline: 1.4723x; 1.1750x over previous
#include <cuda_runtime.h>

#define THREADS 256
#define TILE    512
#define GRID    1184

__device__ float g_partial[GRID];
__device__ unsigned g_count = 0;

// ---------- packed f32x2 helpers ----------
static __device__ __forceinline__ unsigned long long pk2(float a, float b) {
    unsigned long long r;
    asm("mov.b64 %0, {%1,%2};" : "=l"(r) : "f"(a), "f"(b));
    return r;
}
static __device__ __forceinline__ float2 upk2(unsigned long long v) {
    float2 f;
    asm("mov.b64 {%0,%1}, %2;" : "=f"(f.x), "=f"(f.y) : "l"(v));
    return f;
}
static __device__ __forceinline__ unsigned long long fma2_(unsigned long long a,
                                                           unsigned long long b,
                                                           unsigned long long c) {
    unsigned long long d;
    asm("fma.rn.f32x2 %0, %1, %2, %3;" : "=l"(d) : "l"(a), "l"(b), "l"(c));
    return d;
}
static __device__ __forceinline__ unsigned long long add2_(unsigned long long a,
                                                           unsigned long long b) {
    unsigned long long d;
    asm("add.rn.f32x2 %0, %1, %2;" : "=l"(d) : "l"(a), "l"(b));
    return d;
}
static __device__ __forceinline__ unsigned long long mul2_(unsigned long long a,
                                                           unsigned long long b) {
    unsigned long long d;
    asm("mul.rn.f32x2 %0, %1, %2;" : "=l"(d) : "l"(a), "l"(b));
    return d;
}

// exp(x) for a pair of floats, FMA-pipe only (no MUFU).
// exp(x) = 2^(x*log2e) = 2^n * 2^f, n = round(x*log2e), f in [-0.5,0.5]
static __device__ __forceinline__ unsigned long long exp_pair(unsigned long long x2) {
    const float L2E = 1.4426950408889634f;
    const unsigned long long L2E2 = pk2(L2E, L2E);
    const unsigned long long MAG2 = pk2(12582912.0f, 12582912.0f);   // 1.5*2^23
    const unsigned long long N12  = pk2(-1.0f, -1.0f);
    // deg-5 Taylor of 2^f: c_k = (ln2)^k / k!
    const unsigned long long C52 = pk2(1.3333558e-3f, 1.3333558e-3f);
    const unsigned long long C42 = pk2(9.6181291e-3f, 9.6181291e-3f);
    const unsigned long long C32 = pk2(5.5504109e-2f, 5.5504109e-2f);
    const unsigned long long C22 = pk2(2.4022651e-1f, 2.4022651e-1f);
    const unsigned long long C12 = pk2(6.9314718e-1f, 6.9314718e-1f);
    const unsigned long long C02 = pk2(1.0f, 1.0f);

    unsigned long long r2 = fma2_(x2, L2E2, MAG2);   // r = RN(z + MAGIC)
    unsigned long long d2 = fma2_(r2, N12, MAG2);    // d = MAGIC - r = -n (exact)
    unsigned long long f2 = fma2_(x2, L2E2, d2);     // f = z - n
    unsigned long long p2 = fma2_(C52, f2, C42);
    p2 = fma2_(p2, f2, C32);
    p2 = fma2_(p2, f2, C22);
    p2 = fma2_(p2, f2, C12);
    p2 = fma2_(p2, f2, C02);                         // p = 2^f
    float2 r = upk2(r2);
    // bits(r) = 0x4B400000 + n -> (bits << 23) + 1.0f bits = bits of 2^n
    unsigned ia = (unsigned)__float_as_int(r.x) * 8388608u + 0x3f800000u;
    unsigned ib = (unsigned)__float_as_int(r.y) * 8388608u + 0x3f800000u;
    unsigned long long s2 = pk2(__uint_as_float(ia), __uint_as_float(ib));
    return mul2_(p2, s2);
}

// Single-row loss (tail path): lse(x) - v[t].x
static __device__ __forceinline__ float row_loss(const float* __restrict__ x,
                                                 const float* __restrict__ vr) {
    unsigned long long e01 = exp_pair(pk2(x[0], x[1]));
    unsigned long long e23 = exp_pair(pk2(x[2], x[3]));
    unsigned long long e45 = exp_pair(pk2(x[4], x[5]));
    unsigned long long e67 = exp_pair(pk2(x[6], x[7]));
    unsigned long long e89 = exp_pair(pk2(x[8], 0.0f));
    unsigned long long sA = add2_(e01, e23);
    unsigned long long sB = add2_(e45, e67);
    unsigned long long sT = add2_(add2_(sA, sB), e89);
    float2 sf = upk2(sT);
    float sumExp = (sf.x + sf.y) - 1.0f;
    float lse = __logf(sumExp);
    float dot = 0.0f;
    #pragma unroll
    for (int k = 0; k < 9; k++) dot = fmaf(vr[k], x[k], dot);
    return lse - dot;
}

__global__ __launch_bounds__(THREADS, 8)
void cce_fused_kernel(const float* __restrict__ logits,
                      const int* __restrict__ targets,
                      float* __restrict__ out,
                      int B, int NT, float invB) {
    __shared__ float s_log[TILE * 9];
    __shared__ float s_v[81];          // v[t][k] = w[t][k] / S[t]
    __shared__ float s_red[THREADS];
    __shared__ bool  s_last;

    const int tid = threadIdx.x;

    // Build normalized smoothed-label table (9 threads, once per block).
    if (tid < 9) {
        float w[9];
        float S = 0.0f;
        #pragma unroll
        for (int k = 0; k < 9; k++) {
            float ww;
            if (k == tid) {
                ww = 1.0f - 0.1f - 0.2f;                 // main = 0.7
            } else {
                ww = 0.1f / 9.0f;                        // base
                if (k > tid) ww += 0.2f * exp2f((float)(tid - k));
            }
            w[k] = ww;
            S += ww;
        }
        float inv = 1.0f / S;
        #pragma unroll
        for (int k = 0; k < 9; k++) s_v[tid * 9 + k] = w[k] * inv;
    }

    float acc = 0.0f;

    for (int tile = blockIdx.x; tile < NT; tile += GRID) {
        const int base = tile * TILE;
        const int rows = min(TILE, B - base);

        // Stage logits tile: coalesced float4 loads -> shared.
        if (rows == TILE) {
            const float4* g4 = (const float4*)(logits + (size_t)base * 9);
            #pragma unroll
            for (int i = tid; i < TILE * 9 / 4; i += THREADS)
                ((float4*)s_log)[i] = g4[i];
        } else {
            for (int i = tid; i < rows * 9; i += THREADS)
                s_log[i] = logits[(size_t)base * 9 + i];
        }
        const int r0 = tid;
        const int r1 = tid + THREADS;
        int t0 = 0, t1 = 0;
        if (r0 < rows) t0 = targets[base + r0];
        if (r1 < rows) t1 = targets[base + r1];
        __syncthreads();

        if (r1 < rows) {
            // Two-row packed path: lane0 <- row r0, lane1 <- row r1.
            float x0[9], x1[9];
            #pragma unroll
            for (int k = 0; k < 9; k++) x0[k] = s_log[r0 * 9 + k];
            #pragma unroll
            for (int k = 0; k < 9; k++) x1[k] = s_log[r1 * 9 + k];

            unsigned long long se2 = exp_pair(pk2(x0[0], x1[0]));
            #pragma unroll
            for (int k = 1; k < 9; k++)
                se2 = add2_(se2, exp_pair(pk2(x0[k], x1[k])));
            float2 se = upk2(se2);
            float lse0 = __logf(se.x);
            float lse1 = __logf(se.y);

            const float* v0 = &s_v[t0 * 9];
            const float* v1 = &s_v[t1 * 9];
            unsigned long long d2 = pk2(0.0f, 0.0f);
            #pragma unroll
            for (int k = 0; k < 9; k++)
                d2 = fma2_(pk2(v0[k], v1[k]), pk2(x0[k], x1[k]), d2);
            float2 dd = upk2(d2);

            acc += (lse0 - dd.x) + (lse1 - dd.y);
        } else if (r0 < rows) {
            float x[9];
            #pragma unroll
            for (int k = 0; k < 9; k++) x[k] = s_log[r0 * 9 + k];
            acc += row_loss(x, &s_v[t0 * 9]);
        }
        __syncthreads();
    }

    // Deterministic block reduction.
    s_red[tid] = acc;
    __syncthreads();
    #pragma unroll
    for (int s = THREADS / 2; s > 0; s >>= 1) {
        if (tid < s) s_red[tid] += s_red[tid + s];
        __syncthreads();
    }
    if (tid == 0) g_partial[blockIdx.x] = s_red[0];

    // Last-block final reduction (fence + counter; counter self-resets so the
    // kernel is replay-deterministic under graph capture).
    if (tid == 0) {
        __threadfence();
        unsigned prev = atomicAdd(&g_count, 1u);
        s_last = (prev == (unsigned)(gridDim.x - 1));
    }
    __syncthreads();
    if (s_last) {
        float a = 0.0f;
        for (int i = tid; i < GRID; i += THREADS) a += g_partial[i];
        s_red[tid] = a;
        __syncthreads();
        #pragma unroll
        for (int s = THREADS / 2; s > 0; s >>= 1) {
            if (tid < s) s_red[tid] += s_red[tid + s];
            __syncthreads();
        }
        if (tid == 0) {
            out[0] = s_red[0] * invB;
            g_count = 0;                 // reset for next graph replay
        }
    }
}

extern "C" void kernel_launch(void* const* d_in, const int* in_sizes, int n_in,
                              void* d_out, int out_size) {
    const float* logits  = (const float*)d_in[0];
    const int*   targets = (const int*)d_in[1];
    const int B  = in_sizes[1];             // number of rows (targets count)
    const int NT = (B + TILE - 1) / TILE;

    cce_fused_kernel<<<GRID, THREADS>>>(logits, targets, (float*)d_out,
                                        B, NT, 1.0f / (float)B);
}